// round 16
// baseline (speedup 1.0000x reference)
#include <cuda_runtime.h>
#include <math.h>

#define BSZ 8192
#define KC 10
#define NC 100
#define LAMBDA 1.0f
#define WPA 16     // warps per block in phase A
#define WPB 8      // warps per block in phase Q
#define REC 104    // per-batch: D[0..89], YY6[90..95], yw[96..98], pad

__device__ float gRec[BSZ * REC];
__device__ float gQ[BSZ * 56];
__device__ float d_G[KC * KC];
__device__ float d_g[KC];
__device__ float d_bw[32];
__device__ float d_q00;

__device__ __forceinline__ void decode_pair(int u, int& k, int& k2)
{
    k = 0;
    while (u >= KC - k) { u -= KC - k; k++; }
    k2 = k + u;
}

// ---------------- phase A: 512 thr, 16 warps, 1 batch/warp; block 0 computes G,g,q00 ----------------
__global__ __launch_bounds__(512) void phaseA_kernel(const float* __restrict__ y,
                                                     const float* __restrict__ w,
                                                     const float* __restrict__ mk)
{
    __shared__ __align__(16) float sW[100];
    __shared__ float sbw[32];
    __shared__ __align__(16) float sBwT[30 * 100];  // [m][n]
    __shared__ float sPart[256];
    __shared__ __align__(16) float sY[WPA][304];    // [r][n]: r*100+n
    __shared__ float sinvw;
    __shared__ float sS[100];
    __shared__ float sM[10][20];
    __shared__ float sPr[20], sF[10], sHt[10];
    __shared__ float sInv, sden;

    int t = threadIdx.x;

    float wv = (t < 100) ? w[t] : 0.f;
    if (t < 100) sW[t] = wv;
    float a = wv;
#pragma unroll
    for (int off = 16; off > 0; off >>= 1) a += __shfl_xor_sync(~0u, a, off);
    if ((t & 31) == 0) sPart[240 + (t >> 5)] = a;
    __syncthreads();
    if (t == 0) {
        float s = 0.f;
#pragma unroll
        for (int i = 0; i < 16; i++) s += sPart[240 + i];
        sinvw = 1.f / s;
    }
    if (t < 240) {
        int m = t >> 3, h = t & 7;
        const float* mrow = mk + (m % 10) * 300 + (m / 10) * 100;
        float s = 0.f;
        for (int n = h; n < 100; n += 8) s += mrow[n] * sW[n];
        sPart[t] = s;
    }
    __syncthreads();
    if (t < 30) {
        float s = 0.f;
#pragma unroll
        for (int h = 0; h < 8; h++) s += sPart[t * 8 + h];
        sbw[t] = s * sinvw;
    }
    __syncthreads();
    // sBwT[m*100+n] = w[n]*(b[m][n] - bw[m])
    if (t < 240) {
        int m = t >> 3, h = t & 7;
        const float* mrow = mk + (m % 10) * 300 + (m / 10) * 100;
        float bwm = sbw[m];
        float* dst = sBwT + m * 100;
        for (int n = h; n < 100; n += 8)
            dst[n] = sW[n] * (mrow[n] - bwm);
    }
    __syncthreads();

    // ---- warp per batch ----
    int wid = t >> 5, lane = t & 31;
    int b = blockIdx.x * WPA + wid;
    float* Yw = sY[wid];
    float4* Y4 = (float4*)Yw;
    const float4* yb4 = (const float4*)(y + b * 300);

    Y4[lane] = yb4[lane];
    Y4[lane + 32] = yb4[lane + 32];
    if (lane < 11) Y4[lane + 64] = yb4[lane + 64];
    __syncwarp();

    const float4* Y40 = (const float4*)Yw;
    const float4* Y41 = (const float4*)(Yw + 100);
    const float4* Y42 = (const float4*)(Yw + 200);

    // moments: single pass, lanes 0-24 each own 4 consecutive n
    float p0 = 0, p1 = 0, p2 = 0, m00 = 0, m01 = 0, m02 = 0, m11 = 0, m12 = 0, m22 = 0;
    if (lane < 25) {
        float4 w4 = ((const float4*)sW)[lane];
        float4 a0 = Y40[lane], a1 = Y41[lane], a2 = Y42[lane];
        float w0x = w4.x, w0y = w4.y, w0z = w4.z, w0w = w4.w;
        p0 = w0x * a0.x + w0y * a0.y + w0z * a0.z + w0w * a0.w;
        p1 = w0x * a1.x + w0y * a1.y + w0z * a1.z + w0w * a1.w;
        p2 = w0x * a2.x + w0y * a2.y + w0z * a2.z + w0w * a2.w;
        m00 = w0x * a0.x * a0.x + w0y * a0.y * a0.y + w0z * a0.z * a0.z + w0w * a0.w * a0.w;
        m01 = w0x * a0.x * a1.x + w0y * a0.y * a1.y + w0z * a0.z * a1.z + w0w * a0.w * a1.w;
        m02 = w0x * a0.x * a2.x + w0y * a0.y * a2.y + w0z * a0.z * a2.z + w0w * a0.w * a2.w;
        m11 = w0x * a1.x * a1.x + w0y * a1.y * a1.y + w0z * a1.z * a1.z + w0w * a1.w * a1.w;
        m12 = w0x * a1.x * a2.x + w0y * a1.y * a2.y + w0z * a1.z * a2.z + w0w * a1.w * a2.w;
        m22 = w0x * a2.x * a2.x + w0y * a2.y * a2.y + w0z * a2.z * a2.z + w0w * a2.w * a2.w;
    }
#pragma unroll
    for (int off = 16; off > 0; off >>= 1) {
        p0 += __shfl_xor_sync(~0u, p0, off);  p1 += __shfl_xor_sync(~0u, p1, off);
        p2 += __shfl_xor_sync(~0u, p2, off);  m00 += __shfl_xor_sync(~0u, m00, off);
        m01 += __shfl_xor_sync(~0u, m01, off); m02 += __shfl_xor_sync(~0u, m02, off);
        m11 += __shfl_xor_sync(~0u, m11, off); m12 += __shfl_xor_sync(~0u, m12, off);
        m22 += __shfl_xor_sync(~0u, m22, off);
    }
    float iw = sinvw;
    float* rec = gRec + b * REC;

    // D[(3a+j)*10+k]: lane m = a*10+k; Bw column as float4 rows
    if (lane < 30) {
        float a0 = 0, a1 = 0, a2 = 0;
        const float4* BW4 = (const float4*)(sBwT + lane * 100);
#pragma unroll
        for (int c = 0; c < 25; c++) {
            float4 bw = BW4[c];
            float4 q0 = Y40[c], q1 = Y41[c], q2 = Y42[c];
            a0 += q0.x * bw.x + q0.y * bw.y + q0.z * bw.z + q0.w * bw.w;
            a1 += q1.x * bw.x + q1.y * bw.y + q1.z * bw.z + q1.w * bw.w;
            a2 += q2.x * bw.x + q2.y * bw.y + q2.z * bw.z + q2.w * bw.w;
        }
        int base = 30 * (lane / 10) + (lane % 10);
        rec[base] = a0; rec[base + 10] = a1; rec[base + 20] = a2;
    }
    if (lane == 0) {
        rec[90] = m00 - p0 * p0 * iw;
        rec[91] = m01 - p0 * p1 * iw;
        rec[92] = m02 - p0 * p2 * iw;
        rec[93] = m11 - p1 * p1 * iw;
        rec[94] = m12 - p1 * p2 * iw;
        rec[95] = m22 - p2 * p2 * iw;
        rec[96] = p0 * iw; rec[97] = p1 * iw; rec[98] = p2 * iw;
    }

    // ---- block 0 only: batch-invariant G, g, q00 ----
    if (blockIdx.x == 0) {
        float* scratch = (float*)sY;
        __syncthreads();
        if (t < 100) sPart[t] = 1.f / sW[t];
        __syncthreads();
        if (t < 220) {
            int u = t >> 2, h = t & 3;
            int k, k2; decode_pair(u, k, k2);
            float s = 0.f;
            for (int idx = h * 75; idx < h * 75 + 75; idx++) {
                int n = idx / 3, aa = idx % 3;
                s += sPart[n] * sBwT[(aa * 10 + k) * 100 + n] * sBwT[(aa * 10 + k2) * 100 + n];
            }
            scratch[t] = s;
        }
        __syncthreads();
        if (t < 55) {
            int k, k2; decode_pair(t, k, k2);
            float s = scratch[4 * t] + scratch[4 * t + 1] + scratch[4 * t + 2] + scratch[4 * t + 3];
            sS[k * 10 + k2] = s; sS[k2 * 10 + k] = s;
        }
        __syncthreads();
        if (t < 100) {
            int i = t / 10, j = t % 10;
            sM[i][j] = 2.f * (sS[t] + ((i == j) ? LAMBDA : 0.f));
            sM[i][10 + j] = (i == j) ? 1.f : 0.f;
        }
        __syncthreads();
        for (int piv = 0; piv < 10; piv++) {
            if (t < 20) sPr[t] = sM[piv][t];
            if (t >= 32 && t < 42) sF[t - 32] = sM[t - 32][piv];
            if (t == 64) sInv = 1.f / sM[piv][piv];
            __syncthreads();
            if (t < 200) {
                int i = t / 20, j = t % 20;
                float pv = sPr[j] * sInv;
                sM[i][j] = (i == piv) ? pv : sM[i][j] - sF[i] * pv;
            }
            __syncthreads();
        }
        if (t < 10) {
            float s = 0.f;
#pragma unroll
            for (int j = 0; j < 10; j++) s += sM[t][10 + j];
            sHt[t] = s;
        }
        __syncthreads();
        if (t == 0) {
            float dd = 0.f;
#pragma unroll
            for (int i = 0; i < 10; i++) dd += sHt[i];
            sden = dd;
        }
        __syncthreads();
        float denom = sden;
        if (t < 100) d_G[t] = sM[t / 10][10 + (t % 10)] - sHt[t / 10] * sHt[t % 10] / denom;
        if (t < 10) d_g[t] = sHt[t] / denom;
        if (t < 30) d_bw[t] = sbw[t];
        if (t == 0) {
            float q = 0.f;
            for (int i = 0; i < 10; i++) {
                float gi = sHt[i] / denom, ss = 0.f;
                for (int j = 0; j < 10; j++) ss += sS[i * 10 + j] * sHt[j] / denom;
                q += gi * ss + LAMBDA * gi * gi;
            }
            d_q00 = q;
        }
    }
}

// ---------------- phase Q: warp-per-batch Q assembly ----------------
__global__ __launch_bounds__(256) void phaseQ_kernel()
{
    __shared__ float sG[100], sg[12];
    __shared__ float sD[WPB][92], sT[WPB][92], sYY[WPB][12];
    __shared__ float sq00;

    int t = threadIdx.x;
    if (t < 100) sG[t] = d_G[t];
    if (t < 10) sg[t] = d_g[t];
    if (t == 0) sq00 = d_q00;
    __syncthreads();

    int wid = t >> 5, lane = t & 31;
    int b = blockIdx.x * WPB + wid;
    const float* rec = gRec + b * REC;

    for (int i = lane; i < 90; i += 32) sD[wid][i] = rec[i];
    if (lane < 9) {
        const int idx6[9] = {0, 1, 2, 1, 3, 4, 2, 4, 5};
        sYY[wid][lane] = rec[90 + idx6[lane]];
    }
    __syncwarp();

    if (lane < 30) {
        int aa = lane / 10, kp = lane % 10;
        float h0 = 0, h1 = 0, h2 = 0;
#pragma unroll
        for (int k = 0; k < 10; k++) {
            float gv = sG[k * 10 + kp];
            h0 += sD[wid][30 * aa + k] * gv;
            h1 += sD[wid][30 * aa + 10 + k] * gv;
            h2 += sD[wid][30 * aa + 20 + k] * gv;
        }
        sT[wid][30 * aa + kp] = h0; sT[wid][30 * aa + 10 + kp] = h1; sT[wid][30 * aa + 20 + kp] = h2;
    }
    __syncwarp();

    float* qout = gQ + b * 56;
    for (int u = lane; u < 55; u += 32) {
        int I = 0, uu = u;
        while (uu >= 10 - I) { uu -= 10 - I; I++; }
        int J = I + uu;
        float val;
        if (I == 0) {
            if (J == 0) val = sq00;
            else {
                int c = J - 1;
                float acc2 = 0.f;
#pragma unroll
                for (int k = 0; k < 10; k++) acc2 += sD[wid][c * 10 + k] * sg[k];
                val = -acc2;
            }
        } else {
            int c = I - 1, d = J - 1;
            float acc2 = 0.f;
#pragma unroll
            for (int k = 0; k < 10; k++) acc2 += sT[wid][c * 10 + k] * sD[wid][d * 10 + k];
            val = -2.f * acc2;
            if (c / 3 == d / 3) val += sYY[wid][(c % 3) * 3 + (d % 3)];
        }
        qout[u] = val;
    }
    if (lane == 31) qout[55] = 0.f;
}

// ---------------- phase B: 8 batches per warp (8 active lanes) ----------------
__global__ __launch_bounds__(32) void phaseB_kernel(float* __restrict__ out)
{
    int lane = threadIdx.x;
    if (lane >= 8) return;
    int b = blockIdx.x * 8 + lane;
    const float* qin = gQ + b * 56;
    const float* rec = gRec + b * REC;

    float Qp[56];
#pragma unroll
    for (int q4 = 0; q4 < 14; q4++) {
        float4 v = *(const float4*)(qin + q4 * 4);
        Qp[q4 * 4] = v.x; Qp[q4 * 4 + 1] = v.y; Qp[q4 * 4 + 2] = v.z; Qp[q4 * 4 + 3] = v.w;
    }

    float A[10][10];
    {
        int u = 0;
#pragma unroll
        for (int i = 0; i < 10; i++)
#pragma unroll
            for (int j = i; j < 10; j++) {
                A[i][j] = Qp[u]; A[j][i] = Qp[u]; u++;
            }
    }

    float tr = 0.f;
#pragma unroll
    for (int i = 0; i < 10; i++) tr += A[i][i];
    tr = fmaxf(tr, 1e-30f);

    float e[9], beta[8];
#pragma unroll
    for (int k = 0; k < 8; k++) {
        float x0 = A[k + 1][k];
        float snorm = 0.f;
#pragma unroll
        for (int i = k + 2; i < 10; i++) snorm += A[i][k] * A[i][k];
        float nrm = sqrtf(x0 * x0 + snorm);
        float alpha = (x0 >= 0.f) ? -nrm : nrm;
        float v0 = x0 - alpha;
        float vn2 = v0 * v0 + snorm;
        float bt = (vn2 > 1e-30f) ? (2.f / vn2) : 0.f;
        beta[k] = bt;
        e[k] = alpha;
        A[k + 1][k] = v0;

        float p[10];
#pragma unroll
        for (int i = k + 1; i < 10; i++) {
            float s = 0.f;
#pragma unroll
            for (int j = k + 1; j < 10; j++) s += A[i][j] * A[j][k];
            p[i] = bt * s;
        }
        float vp = 0.f;
#pragma unroll
        for (int i = k + 1; i < 10; i++) vp += p[i] * A[i][k];
        float hb = 0.5f * bt * vp;
#pragma unroll
        for (int i = k + 1; i < 10; i++) p[i] -= hb * A[i][k];
#pragma unroll
        for (int i = k + 1; i < 10; i++)
#pragma unroll
            for (int j = k + 1; j < 10; j++)
                A[i][j] -= A[i][k] * p[j] + p[i] * A[j][k];
    }
    e[8] = A[9][8];
    float d[10];
#pragma unroll
    for (int i = 0; i < 10; i++) d[i] = A[i][i];

    float e2[9];
#pragma unroll
    for (int i = 0; i < 9; i++) e2[i] = e[i] * e[i];

    float lo = d[0] - fabsf(e[0]);
    float hi = d[0];
#pragma unroll
    for (int i = 1; i < 10; i++) {
        float g = d[i] - fabsf(e[i - 1]) - ((i < 9) ? fabsf(e[i]) : 0.f);
        lo = fminf(lo, g);
        hi = fminf(hi, d[i]);
    }
    float peps = tr * 1e-10f + 1e-30f;

#pragma unroll 1
    for (int it = 0; it < 14; it++) {
        float mid = 0.5f * (lo + hi);
        float q = d[0] - mid;
        int cnt = (q < 0.f);
#pragma unroll
        for (int i = 1; i < 10; i++) {
            float den = (fabsf(q) < peps) ? ((q < 0.f) ? -peps : peps) : q;
            q = d[i] - mid - __fdividef(e2[i - 1], den);
            cnt += (q < 0.f);
        }
        lo = (cnt >= 1) ? lo : mid;
        hi = (cnt >= 1) ? mid : hi;
    }
    float sigma = lo;

    float cf[10], lf[9], icf[10];
    float teps = tr * 1e-12f + 1e-32f;
    {
        float q = d[0] - sigma;
        cf[0] = (fabsf(q) < teps) ? ((q < 0.f) ? -teps : teps) : q;
#pragma unroll
        for (int i = 1; i < 10; i++) {
            lf[i - 1] = __fdividef(e[i - 1], cf[i - 1]);
            q = d[i] - sigma - lf[i - 1] * e[i - 1];
            cf[i] = (fabsf(q) < teps) ? ((q < 0.f) ? -teps : teps) : q;
        }
#pragma unroll
        for (int i = 0; i < 10; i++) icf[i] = __frcp_rn(cf[i]);
    }

    float z[10];
#pragma unroll
    for (int i = 0; i < 10; i++) z[i] = ((i & 1) ? -1.f : 1.f) + 0.21f * (float)i;
#pragma unroll 1
    for (int it = 0; it < 3; it++) {
        float yv[10];
        yv[0] = z[0];
#pragma unroll
        for (int i = 1; i < 10; i++) yv[i] = z[i] - lf[i - 1] * yv[i - 1];
        z[9] = yv[9] * icf[9];
#pragma unroll
        for (int i = 8; i >= 0; i--) z[i] = (yv[i] - e[i] * z[i + 1]) * icf[i];
        float nn = 0.f;
#pragma unroll
        for (int i = 0; i < 10; i++) nn += z[i] * z[i];
        float inr = rsqrtf(fmaxf(nn, 1e-30f));
#pragma unroll
        for (int i = 0; i < 10; i++) {
            float zv = z[i] * inr;
            z[i] = fminf(fmaxf(zv, -2.f), 2.f);
        }
    }

#pragma unroll
    for (int k = 7; k >= 0; k--) {
        float t2 = 0.f;
#pragma unroll
        for (int i = k + 1; i < 10; i++) t2 += A[i][k] * z[i];
        t2 *= beta[k];
#pragma unroll
        for (int i = k + 1; i < 10; i++) z[i] -= t2 * A[i][k];
    }

    float inv0 = 1.f / z[0];

    float Rv[9];
#pragma unroll
    for (int c = 0; c < 9; c++) Rv[c] = z[1 + c] * inv0;

    float D2[90];
#pragma unroll
    for (int q4 = 0; q4 < 22; q4++) {
        float4 v = *(const float4*)(rec + q4 * 4);
        D2[q4 * 4] = v.x; D2[q4 * 4 + 1] = v.y; D2[q4 * 4 + 2] = v.z; D2[q4 * 4 + 3] = v.w;
    }
    D2[88] = rec[88]; D2[89] = rec[89];
    float yw0 = rec[96], yw1 = rec[97], yw2 = rec[98];

    float uvec[10];
#pragma unroll
    for (int k = 0; k < 10; k++) {
        float s2 = 0.f;
#pragma unroll
        for (int c = 0; c < 9; c++) s2 += Rv[c] * D2[c * 10 + k];
        uvec[k] = s2;
    }
    float cv[10];
#pragma unroll
    for (int k = 0; k < 10; k++) {
        float s2 = 0.f;
#pragma unroll
        for (int kp = 0; kp < 10; kp++) s2 += d_G[k * 10 + kp] * uvec[kp];
        cv[k] = 2.f * s2 + d_g[k];
    }
    float inner[3];
#pragma unroll
    for (int a = 0; a < 3; a++) {
        float s2 = 0.f;
#pragma unroll
        for (int k = 0; k < 10; k++) s2 += d_bw[a * 10 + k] * cv[k];
        inner[a] = s2;
    }

#pragma unroll
    for (int r = 0; r < 3; r++)
#pragma unroll
        for (int a = 0; a < 3; a++)
            out[b * 9 + r * 3 + a] = Rv[3 * a + r];
    float ywv[3] = {yw0, yw1, yw2};
#pragma unroll
    for (int j = 0; j < 3; j++) {
        float tv = ywv[j];
#pragma unroll
        for (int a = 0; a < 3; a++) tv -= Rv[3 * a + j] * inner[a];
        out[BSZ * 9 + b * 3 + j] = tv;
    }
#pragma unroll
    for (int k = 0; k < 10; k++)
        out[BSZ * 12 + b * 10 + k] = cv[k];
}

extern "C" void kernel_launch(void* const* d_in, const int* in_sizes, int n_in,
                              void* d_out, int out_size)
{
    const float* y  = (const float*)d_in[0];
    const float* w  = (const float*)d_in[1];
    const float* mk = (const float*)d_in[2];
    float* out = (float*)d_out;
    phaseA_kernel<<<BSZ / WPA, 512>>>(y, w, mk);
    phaseQ_kernel<<<BSZ / WPB, 256>>>();
    phaseB_kernel<<<BSZ / 8, 32>>>(out);
}

// round 17
// speedup vs baseline: 1.0486x; 1.0486x over previous
#include <cuda_runtime.h>
#include <math.h>

#define BSZ 8192
#define KC 10
#define NC 100
#define LAMBDA 1.0f
#define WPB 8
#define REC 104    // per-batch: D[0..89], YY6[90..95], yw[96..98], pad

__device__ float gRec[BSZ * REC];
__device__ float gQ[BSZ * 56];
__device__ float d_G[KC * KC];
__device__ float d_g[KC];
__device__ float d_bw[32];
__device__ float d_q00;

__device__ __forceinline__ void decode_pair(int u, int& k, int& k2)
{
    k = 0;
    while (u >= KC - k) { u -= KC - k; k++; }
    k2 = k + u;
}

// ---------------- phase A: 256 thr, 8 warps, 1 batch/warp; block 0 computes G,g,q00 ----------------
__global__ __launch_bounds__(256) void phaseA_kernel(const float* __restrict__ y,
                                                     const float* __restrict__ w,
                                                     const float* __restrict__ mk)
{
    __shared__ __align__(16) float sW[100];
    __shared__ float sbw[32];
    __shared__ __align__(16) float sBwT[30 * 100];  // [m][n]
    __shared__ float sPart[248];
    __shared__ __align__(16) float sY[WPB][304];    // [r][n]: r*100+n
    __shared__ float sinvw;
    __shared__ float sS[100];
    __shared__ float sM[10][20];
    __shared__ float sPr[20], sF[10], sHt[10];
    __shared__ float sInv, sden;

    int t = threadIdx.x;

    float wv = (t < 100) ? w[t] : 0.f;
    if (t < 100) sW[t] = wv;
    float a = wv;
#pragma unroll
    for (int off = 16; off > 0; off >>= 1) a += __shfl_xor_sync(~0u, a, off);
    if ((t & 31) == 0) sPart[240 + (t >> 5)] = a;
    __syncthreads();
    if (t == 0) {
        float s = 0.f;
#pragma unroll
        for (int i = 0; i < 8; i++) s += sPart[240 + i];
        sinvw = 1.f / s;
    }
    if (t < 240) {
        int m = t >> 3, h = t & 7;
        const float* mrow = mk + (m % 10) * 300 + (m / 10) * 100;
        float s = 0.f;
        for (int n = h; n < 100; n += 8) s += mrow[n] * sW[n];
        sPart[t] = s;
    }
    __syncthreads();
    if (t < 30) {
        float s = 0.f;
#pragma unroll
        for (int h = 0; h < 8; h++) s += sPart[t * 8 + h];
        sbw[t] = s * sinvw;
    }
    __syncthreads();
    // sBwT[m*100+n] = w[n]*(b[m][n] - bw[m])
    if (t < 240) {
        int m = t >> 3, h = t & 7;
        const float* mrow = mk + (m % 10) * 300 + (m / 10) * 100;
        float bwm = sbw[m];
        float* dst = sBwT + m * 100;
        for (int n = h; n < 100; n += 8)
            dst[n] = sW[n] * (mrow[n] - bwm);
    }
    __syncthreads();

    // ---- warp per batch ----
    int wid = t >> 5, lane = t & 31;
    int b = blockIdx.x * WPB + wid;
    float* Yw = sY[wid];
    float4* Y4 = (float4*)Yw;
    const float4* yb4 = (const float4*)(y + b * 300);

    Y4[lane] = yb4[lane];
    Y4[lane + 32] = yb4[lane + 32];
    if (lane < 11) Y4[lane + 64] = yb4[lane + 64];
    __syncwarp();

    const float4* Y40 = (const float4*)Yw;
    const float4* Y41 = (const float4*)(Yw + 100);
    const float4* Y42 = (const float4*)(Yw + 200);

    // moments: single pass, lanes 0-24 each own 4 consecutive n
    float p0 = 0, p1 = 0, p2 = 0, m00 = 0, m01 = 0, m02 = 0, m11 = 0, m12 = 0, m22 = 0;
    if (lane < 25) {
        float4 w4 = ((const float4*)sW)[lane];
        float4 a0 = Y40[lane], a1 = Y41[lane], a2 = Y42[lane];
        p0 = w4.x * a0.x + w4.y * a0.y + w4.z * a0.z + w4.w * a0.w;
        p1 = w4.x * a1.x + w4.y * a1.y + w4.z * a1.z + w4.w * a1.w;
        p2 = w4.x * a2.x + w4.y * a2.y + w4.z * a2.z + w4.w * a2.w;
        m00 = w4.x * a0.x * a0.x + w4.y * a0.y * a0.y + w4.z * a0.z * a0.z + w4.w * a0.w * a0.w;
        m01 = w4.x * a0.x * a1.x + w4.y * a0.y * a1.y + w4.z * a0.z * a1.z + w4.w * a0.w * a1.w;
        m02 = w4.x * a0.x * a2.x + w4.y * a0.y * a2.y + w4.z * a0.z * a2.z + w4.w * a0.w * a2.w;
        m11 = w4.x * a1.x * a1.x + w4.y * a1.y * a1.y + w4.z * a1.z * a1.z + w4.w * a1.w * a1.w;
        m12 = w4.x * a1.x * a2.x + w4.y * a1.y * a2.y + w4.z * a1.z * a2.z + w4.w * a1.w * a2.w;
        m22 = w4.x * a2.x * a2.x + w4.y * a2.y * a2.y + w4.z * a2.z * a2.z + w4.w * a2.w * a2.w;
    }
#pragma unroll
    for (int off = 16; off > 0; off >>= 1) {
        p0 += __shfl_xor_sync(~0u, p0, off);  p1 += __shfl_xor_sync(~0u, p1, off);
        p2 += __shfl_xor_sync(~0u, p2, off);  m00 += __shfl_xor_sync(~0u, m00, off);
        m01 += __shfl_xor_sync(~0u, m01, off); m02 += __shfl_xor_sync(~0u, m02, off);
        m11 += __shfl_xor_sync(~0u, m11, off); m12 += __shfl_xor_sync(~0u, m12, off);
        m22 += __shfl_xor_sync(~0u, m22, off);
    }
    float iw = sinvw;
    float* rec = gRec + b * REC;

    // D[(3a+j)*10+k]: lane m = a*10+k; Bw column as float4 rows
    if (lane < 30) {
        float a0 = 0, a1 = 0, a2 = 0;
        const float4* BW4 = (const float4*)(sBwT + lane * 100);
#pragma unroll
        for (int c = 0; c < 25; c++) {
            float4 bw = BW4[c];
            float4 q0 = Y40[c], q1 = Y41[c], q2 = Y42[c];
            a0 += q0.x * bw.x + q0.y * bw.y + q0.z * bw.z + q0.w * bw.w;
            a1 += q1.x * bw.x + q1.y * bw.y + q1.z * bw.z + q1.w * bw.w;
            a2 += q2.x * bw.x + q2.y * bw.y + q2.z * bw.z + q2.w * bw.w;
        }
        int base = 30 * (lane / 10) + (lane % 10);
        rec[base] = a0; rec[base + 10] = a1; rec[base + 20] = a2;
    }
    if (lane == 0) {
        rec[90] = m00 - p0 * p0 * iw;
        rec[91] = m01 - p0 * p1 * iw;
        rec[92] = m02 - p0 * p2 * iw;
        rec[93] = m11 - p1 * p1 * iw;
        rec[94] = m12 - p1 * p2 * iw;
        rec[95] = m22 - p2 * p2 * iw;
        rec[96] = p0 * iw; rec[97] = p1 * iw; rec[98] = p2 * iw;
    }

    // ---- block 0 only: batch-invariant G, g, q00 ----
    if (blockIdx.x == 0) {
        float* scratch = (float*)sY;
        __syncthreads();
        if (t < 100) sPart[t] = 1.f / sW[t];
        __syncthreads();
        if (t < 220) {
            int u = t >> 2, h = t & 3;
            int k, k2; decode_pair(u, k, k2);
            float s = 0.f;
            for (int idx = h * 75; idx < h * 75 + 75; idx++) {
                int n = idx / 3, aa = idx % 3;
                s += sPart[n] * sBwT[(aa * 10 + k) * 100 + n] * sBwT[(aa * 10 + k2) * 100 + n];
            }
            scratch[t] = s;
        }
        __syncthreads();
        if (t < 55) {
            int k, k2; decode_pair(t, k, k2);
            float s = scratch[4 * t] + scratch[4 * t + 1] + scratch[4 * t + 2] + scratch[4 * t + 3];
            sS[k * 10 + k2] = s; sS[k2 * 10 + k] = s;
        }
        __syncthreads();
        if (t < 100) {
            int i = t / 10, j = t % 10;
            sM[i][j] = 2.f * (sS[t] + ((i == j) ? LAMBDA : 0.f));
            sM[i][10 + j] = (i == j) ? 1.f : 0.f;
        }
        __syncthreads();
        for (int piv = 0; piv < 10; piv++) {
            if (t < 20) sPr[t] = sM[piv][t];
            if (t >= 32 && t < 42) sF[t - 32] = sM[t - 32][piv];
            if (t == 64) sInv = 1.f / sM[piv][piv];
            __syncthreads();
            if (t < 200) {
                int i = t / 20, j = t % 20;
                float pv = sPr[j] * sInv;
                sM[i][j] = (i == piv) ? pv : sM[i][j] - sF[i] * pv;
            }
            __syncthreads();
        }
        if (t < 10) {
            float s = 0.f;
#pragma unroll
            for (int j = 0; j < 10; j++) s += sM[t][10 + j];
            sHt[t] = s;
        }
        __syncthreads();
        if (t == 0) {
            float dd = 0.f;
#pragma unroll
            for (int i = 0; i < 10; i++) dd += sHt[i];
            sden = dd;
        }
        __syncthreads();
        float denom = sden;
        if (t < 100) d_G[t] = sM[t / 10][10 + (t % 10)] - sHt[t / 10] * sHt[t % 10] / denom;
        if (t < 10) d_g[t] = sHt[t] / denom;
        if (t < 30) d_bw[t] = sbw[t];
        if (t == 0) {
            float q = 0.f;
            for (int i = 0; i < 10; i++) {
                float gi = sHt[i] / denom, ss = 0.f;
                for (int j = 0; j < 10; j++) ss += sS[i * 10 + j] * sHt[j] / denom;
                q += gi * ss + LAMBDA * gi * gi;
            }
            d_q00 = q;
        }
    }
}

// ---------------- phase Q: warp-per-batch Q assembly ----------------
__global__ __launch_bounds__(256) void phaseQ_kernel()
{
    __shared__ float sG[100], sg[12];
    __shared__ float sD[WPB][92], sT[WPB][92], sYY[WPB][12];
    __shared__ float sq00;

    int t = threadIdx.x;
    if (t < 100) sG[t] = d_G[t];
    if (t < 10) sg[t] = d_g[t];
    if (t == 0) sq00 = d_q00;
    __syncthreads();

    int wid = t >> 5, lane = t & 31;
    int b = blockIdx.x * WPB + wid;
    const float* rec = gRec + b * REC;

    for (int i = lane; i < 90; i += 32) sD[wid][i] = rec[i];
    if (lane < 9) {
        const int idx6[9] = {0, 1, 2, 1, 3, 4, 2, 4, 5};
        sYY[wid][lane] = rec[90 + idx6[lane]];
    }
    __syncwarp();

    if (lane < 30) {
        int aa = lane / 10, kp = lane % 10;
        float h0 = 0, h1 = 0, h2 = 0;
#pragma unroll
        for (int k = 0; k < 10; k++) {
            float gv = sG[k * 10 + kp];
            h0 += sD[wid][30 * aa + k] * gv;
            h1 += sD[wid][30 * aa + 10 + k] * gv;
            h2 += sD[wid][30 * aa + 20 + k] * gv;
        }
        sT[wid][30 * aa + kp] = h0; sT[wid][30 * aa + 10 + kp] = h1; sT[wid][30 * aa + 20 + kp] = h2;
    }
    __syncwarp();

    float* qout = gQ + b * 56;
    for (int u = lane; u < 55; u += 32) {
        int I = 0, uu = u;
        while (uu >= 10 - I) { uu -= 10 - I; I++; }
        int J = I + uu;
        float val;
        if (I == 0) {
            if (J == 0) val = sq00;
            else {
                int c = J - 1;
                float acc2 = 0.f;
#pragma unroll
                for (int k = 0; k < 10; k++) acc2 += sD[wid][c * 10 + k] * sg[k];
                val = -acc2;
            }
        } else {
            int c = I - 1, d = J - 1;
            float acc2 = 0.f;
#pragma unroll
            for (int k = 0; k < 10; k++) acc2 += sT[wid][c * 10 + k] * sD[wid][d * 10 + k];
            val = -2.f * acc2;
            if (c / 3 == d / 3) val += sYY[wid][(c % 3) * 3 + (d % 3)];
        }
        qout[u] = val;
    }
    if (lane == 31) qout[55] = 0.f;
}

// ---------------- phase B: 8 batches per warp (8 active lanes) ----------------
__global__ __launch_bounds__(32) void phaseB_kernel(float* __restrict__ out)
{
    int lane = threadIdx.x;
    if (lane >= 8) return;
    int b = blockIdx.x * 8 + lane;
    const float* qin = gQ + b * 56;
    const float* rec = gRec + b * REC;

    float Qp[56];
#pragma unroll
    for (int q4 = 0; q4 < 14; q4++) {
        float4 v = *(const float4*)(qin + q4 * 4);
        Qp[q4 * 4] = v.x; Qp[q4 * 4 + 1] = v.y; Qp[q4 * 4 + 2] = v.z; Qp[q4 * 4 + 3] = v.w;
    }

    float A[10][10];
    {
        int u = 0;
#pragma unroll
        for (int i = 0; i < 10; i++)
#pragma unroll
            for (int j = i; j < 10; j++) {
                A[i][j] = Qp[u]; A[j][i] = Qp[u]; u++;
            }
    }

    float tr = 0.f;
#pragma unroll
    for (int i = 0; i < 10; i++) tr += A[i][i];
    tr = fmaxf(tr, 1e-30f);

    float e[9], beta[8];
#pragma unroll
    for (int k = 0; k < 8; k++) {
        float x0 = A[k + 1][k];
        float snorm = 0.f;
#pragma unroll
        for (int i = k + 2; i < 10; i++) snorm += A[i][k] * A[i][k];
        float nrm = sqrtf(x0 * x0 + snorm);
        float alpha = (x0 >= 0.f) ? -nrm : nrm;
        float v0 = x0 - alpha;
        float vn2 = v0 * v0 + snorm;
        float bt = (vn2 > 1e-30f) ? (2.f / vn2) : 0.f;
        beta[k] = bt;
        e[k] = alpha;
        A[k + 1][k] = v0;

        float p[10];
#pragma unroll
        for (int i = k + 1; i < 10; i++) {
            float s = 0.f;
#pragma unroll
            for (int j = k + 1; j < 10; j++) s += A[i][j] * A[j][k];
            p[i] = bt * s;
        }
        float vp = 0.f;
#pragma unroll
        for (int i = k + 1; i < 10; i++) vp += p[i] * A[i][k];
        float hb = 0.5f * bt * vp;
#pragma unroll
        for (int i = k + 1; i < 10; i++) p[i] -= hb * A[i][k];
#pragma unroll
        for (int i = k + 1; i < 10; i++)
#pragma unroll
            for (int j = k + 1; j < 10; j++)
                A[i][j] -= A[i][k] * p[j] + p[i] * A[j][k];
    }
    e[8] = A[9][8];
    float d[10];
#pragma unroll
    for (int i = 0; i < 10; i++) d[i] = A[i][i];

    float e2[9];
#pragma unroll
    for (int i = 0; i < 9; i++) e2[i] = e[i] * e[i];

    float lo = d[0] - fabsf(e[0]);
    float hi = d[0];
#pragma unroll
    for (int i = 1; i < 10; i++) {
        float g = d[i] - fabsf(e[i - 1]) - ((i < 9) ? fabsf(e[i]) : 0.f);
        lo = fminf(lo, g);
        hi = fminf(hi, d[i]);
    }
    float peps = tr * 1e-10f + 1e-30f;

#pragma unroll 1
    for (int it = 0; it < 14; it++) {
        float mid = 0.5f * (lo + hi);
        float q = d[0] - mid;
        int cnt = (q < 0.f);
#pragma unroll
        for (int i = 1; i < 10; i++) {
            float den = (fabsf(q) < peps) ? ((q < 0.f) ? -peps : peps) : q;
            q = d[i] - mid - __fdividef(e2[i - 1], den);
            cnt += (q < 0.f);
        }
        lo = (cnt >= 1) ? lo : mid;
        hi = (cnt >= 1) ? mid : hi;
    }
    float sigma = lo;

    float cf[10], lf[9], icf[10];
    float teps = tr * 1e-12f + 1e-32f;
    {
        float q = d[0] - sigma;
        cf[0] = (fabsf(q) < teps) ? ((q < 0.f) ? -teps : teps) : q;
#pragma unroll
        for (int i = 1; i < 10; i++) {
            lf[i - 1] = __fdividef(e[i - 1], cf[i - 1]);
            q = d[i] - sigma - lf[i - 1] * e[i - 1];
            cf[i] = (fabsf(q) < teps) ? ((q < 0.f) ? -teps : teps) : q;
        }
#pragma unroll
        for (int i = 0; i < 10; i++) icf[i] = __frcp_rn(cf[i]);
    }

    float z[10];
#pragma unroll
    for (int i = 0; i < 10; i++) z[i] = ((i & 1) ? -1.f : 1.f) + 0.21f * (float)i;
#pragma unroll 1
    for (int it = 0; it < 3; it++) {
        float yv[10];
        yv[0] = z[0];
#pragma unroll
        for (int i = 1; i < 10; i++) yv[i] = z[i] - lf[i - 1] * yv[i - 1];
        z[9] = yv[9] * icf[9];
#pragma unroll
        for (int i = 8; i >= 0; i--) z[i] = (yv[i] - e[i] * z[i + 1]) * icf[i];
        float nn = 0.f;
#pragma unroll
        for (int i = 0; i < 10; i++) nn += z[i] * z[i];
        float inr = rsqrtf(fmaxf(nn, 1e-30f));
#pragma unroll
        for (int i = 0; i < 10; i++) {
            float zv = z[i] * inr;
            z[i] = fminf(fmaxf(zv, -2.f), 2.f);
        }
    }

#pragma unroll
    for (int k = 7; k >= 0; k--) {
        float t2 = 0.f;
#pragma unroll
        for (int i = k + 1; i < 10; i++) t2 += A[i][k] * z[i];
        t2 *= beta[k];
#pragma unroll
        for (int i = k + 1; i < 10; i++) z[i] -= t2 * A[i][k];
    }

    float inv0 = 1.f / z[0];

    float Rv[9];
#pragma unroll
    for (int c = 0; c < 9; c++) Rv[c] = z[1 + c] * inv0;

    float D2[90];
#pragma unroll
    for (int q4 = 0; q4 < 22; q4++) {
        float4 v = *(const float4*)(rec + q4 * 4);
        D2[q4 * 4] = v.x; D2[q4 * 4 + 1] = v.y; D2[q4 * 4 + 2] = v.z; D2[q4 * 4 + 3] = v.w;
    }
    D2[88] = rec[88]; D2[89] = rec[89];
    float yw0 = rec[96], yw1 = rec[97], yw2 = rec[98];

    float uvec[10];
#pragma unroll
    for (int k = 0; k < 10; k++) {
        float s2 = 0.f;
#pragma unroll
        for (int c = 0; c < 9; c++) s2 += Rv[c] * D2[c * 10 + k];
        uvec[k] = s2;
    }
    float cv[10];
#pragma unroll
    for (int k = 0; k < 10; k++) {
        float s2 = 0.f;
#pragma unroll
        for (int kp = 0; kp < 10; kp++) s2 += d_G[k * 10 + kp] * uvec[kp];
        cv[k] = 2.f * s2 + d_g[k];
    }
    float inner[3];
#pragma unroll
    for (int a = 0; a < 3; a++) {
        float s2 = 0.f;
#pragma unroll
        for (int k = 0; k < 10; k++) s2 += d_bw[a * 10 + k] * cv[k];
        inner[a] = s2;
    }

#pragma unroll
    for (int r = 0; r < 3; r++)
#pragma unroll
        for (int a = 0; a < 3; a++)
            out[b * 9 + r * 3 + a] = Rv[3 * a + r];
    float ywv[3] = {yw0, yw1, yw2};
#pragma unroll
    for (int j = 0; j < 3; j++) {
        float tv = ywv[j];
#pragma unroll
        for (int a = 0; a < 3; a++) tv -= Rv[3 * a + j] * inner[a];
        out[BSZ * 9 + b * 3 + j] = tv;
    }
#pragma unroll
    for (int k = 0; k < 10; k++)
        out[BSZ * 12 + b * 10 + k] = cv[k];
}

extern "C" void kernel_launch(void* const* d_in, const int* in_sizes, int n_in,
                              void* d_out, int out_size)
{
    const float* y  = (const float*)d_in[0];
    const float* w  = (const float*)d_in[1];
    const float* mk = (const float*)d_in[2];
    float* out = (float*)d_out;
    phaseA_kernel<<<BSZ / WPB, 256>>>(y, w, mk);
    phaseQ_kernel<<<BSZ / WPB, 256>>>();
    phaseB_kernel<<<BSZ / 8, 32>>>(out);
}